// round 1
// baseline (speedup 1.0000x reference)
#include <cuda_runtime.h>
#include <math.h>

#define Bsz   2
#define Sseq  2048
#define Dm    1024
#define Hh    16
#define DHd   64
#define BLKs  128
#define NBl   16
#define Mrows (Bsz * Sseq)   // 4096
#define Dff   (4 * Dm)       // 4096

// ---------------- scratch (static device allocations are allowed) ----------
__device__ float g_h  [Mrows * Dm];
__device__ float g_q  [Mrows * Dm];
__device__ float g_k  [Mrows * Dm];
__device__ float g_v  [Mrows * Dm];
__device__ float g_ctx[Mrows * Dm];
__device__ float g_x1 [Mrows * Dm];
__device__ float g_h2 [Mrows * Dm];
__device__ float g_ff [Mrows * Dff];

// ---------------- LayerNorm: one block per row, 256 threads ----------------
__global__ __launch_bounds__(256) void ln_kernel(
    const float* __restrict__ x, const float* __restrict__ g,
    const float* __restrict__ b, float* __restrict__ out)
{
    const int row = blockIdx.x;
    const int t   = threadIdx.x;
    const float4 v = reinterpret_cast<const float4*>(x + (size_t)row * Dm)[t];

    float s  = v.x + v.y + v.z + v.w;
    float s2 = v.x * v.x + v.y * v.y + v.z * v.z + v.w * v.w;

    __shared__ float red[16];
    #pragma unroll
    for (int o = 16; o; o >>= 1) {
        s  += __shfl_xor_sync(0xffffffffu, s,  o);
        s2 += __shfl_xor_sync(0xffffffffu, s2, o);
    }
    const int w = t >> 5, l = t & 31;
    if (l == 0) { red[w] = s; red[w + 8] = s2; }
    __syncthreads();
    if (w == 0) {
        float a  = (l < 8) ? red[l]     : 0.f;
        float a2 = (l < 8) ? red[l + 8] : 0.f;
        #pragma unroll
        for (int o = 4; o; o >>= 1) {
            a  += __shfl_xor_sync(0xffffffffu, a,  o);
            a2 += __shfl_xor_sync(0xffffffffu, a2, o);
        }
        if (l == 0) { red[0] = a; red[1] = a2; }
    }
    __syncthreads();

    const float mean = red[0] * (1.f / Dm);
    const float var  = red[1] * (1.f / Dm) - mean * mean;
    const float rs   = rsqrtf(var + 1e-5f);

    const float4 gg = reinterpret_cast<const float4*>(g)[t];
    const float4 bb = reinterpret_cast<const float4*>(b)[t];
    float4 o4;
    o4.x = (v.x - mean) * rs * gg.x + bb.x;
    o4.y = (v.y - mean) * rs * gg.y + bb.y;
    o4.z = (v.z - mean) * rs * gg.z + bb.z;
    o4.w = (v.w - mean) * rs * gg.w + bb.w;
    reinterpret_cast<float4*>(out + (size_t)row * Dm)[t] = o4;
}

// ---------------- SGEMM 128x128x8, 256 threads, 8x8 per thread -------------
// EPI: 0 = +bias ; 1 = +bias then gelu(exact) ; 2 = +bias +residual
__device__ __forceinline__ float gelu_exact(float x) {
    return 0.5f * x * (1.0f + erff(x * 0.70710678118654752f));
}

template<int EPI>
__global__ __launch_bounds__(256) void sgemm_kernel(
    const float* __restrict__ A, const float* __restrict__ Bm,
    const float* __restrict__ bias, const float* __restrict__ res,
    float* __restrict__ C, int M, int N, int K)
{
    __shared__ float As[2][8][128];
    __shared__ float Bs[2][8][128];

    const int tid = threadIdx.x;
    const int bm  = blockIdx.y * 128;
    const int bn  = blockIdx.x * 128;

    const int arow = tid >> 1;          // 0..127
    const int acol = (tid & 1) * 4;     // 0 or 4
    const int brow = tid >> 5;          // 0..7
    const int bcol = (tid & 31) * 4;    // 0..124

    const float* Ap = A  + (size_t)(bm + arow) * K + acol;
    const float* Bp = Bm + (size_t)brow * N + bn + bcol;

    const int ty = tid >> 4;   // 0..15
    const int tx = tid & 15;   // 0..15

    float acc[8][8];
    #pragma unroll
    for (int i = 0; i < 8; i++)
        #pragma unroll
        for (int j = 0; j < 8; j++) acc[i][j] = 0.f;

    // preload tile 0
    float4 a4 = *reinterpret_cast<const float4*>(Ap);
    float4 b4 = *reinterpret_cast<const float4*>(Bp);
    int buf = 0;
    As[0][acol + 0][arow] = a4.x;
    As[0][acol + 1][arow] = a4.y;
    As[0][acol + 2][arow] = a4.z;
    As[0][acol + 3][arow] = a4.w;
    *reinterpret_cast<float4*>(&Bs[0][brow][bcol]) = b4;
    __syncthreads();

    const int nk = K >> 3;
    for (int it = 0; it < nk; it++) {
        const bool pref = (it + 1 < nk);
        float4 a4n, b4n;
        if (pref) {
            a4n = *reinterpret_cast<const float4*>(Ap + (size_t)(it + 1) * 8);
            b4n = *reinterpret_cast<const float4*>(Bp + (size_t)(it + 1) * 8 * N);
        }
        #pragma unroll
        for (int kk = 0; kk < 8; kk++) {
            float af[8], bf[8];
            *reinterpret_cast<float4*>(af)     = *reinterpret_cast<float4*>(&As[buf][kk][ty * 8]);
            *reinterpret_cast<float4*>(af + 4) = *reinterpret_cast<float4*>(&As[buf][kk][ty * 8 + 4]);
            *reinterpret_cast<float4*>(bf)     = *reinterpret_cast<float4*>(&Bs[buf][kk][tx * 8]);
            *reinterpret_cast<float4*>(bf + 4) = *reinterpret_cast<float4*>(&Bs[buf][kk][tx * 8 + 4]);
            #pragma unroll
            for (int i = 0; i < 8; i++)
                #pragma unroll
                for (int j = 0; j < 8; j++)
                    acc[i][j] = fmaf(af[i], bf[j], acc[i][j]);
        }
        if (pref) {
            buf ^= 1;
            As[buf][acol + 0][arow] = a4n.x;
            As[buf][acol + 1][arow] = a4n.y;
            As[buf][acol + 2][arow] = a4n.z;
            As[buf][acol + 3][arow] = a4n.w;
            *reinterpret_cast<float4*>(&Bs[buf][brow][bcol]) = b4n;
        }
        __syncthreads();
    }

    // epilogue
    #pragma unroll
    for (int i = 0; i < 8; i++) {
        const int row = bm + ty * 8 + i;
        #pragma unroll
        for (int j = 0; j < 8; j += 4) {
            const int col = bn + tx * 8 + j;
            float4 o;
            o.x = acc[i][j + 0] + bias[col + 0];
            o.y = acc[i][j + 1] + bias[col + 1];
            o.z = acc[i][j + 2] + bias[col + 2];
            o.w = acc[i][j + 3] + bias[col + 3];
            if (EPI == 1) {
                o.x = gelu_exact(o.x); o.y = gelu_exact(o.y);
                o.z = gelu_exact(o.z); o.w = gelu_exact(o.w);
            }
            if (EPI == 2) {
                const float4 r4 = *reinterpret_cast<const float4*>(&res[(size_t)row * N + col]);
                o.x += r4.x; o.y += r4.y; o.z += r4.z; o.w += r4.w;
            }
            *reinterpret_cast<float4*>(&C[(size_t)row * N + col]) = o;
        }
    }
}

// ---------------- block-sparse flash attention ------------------------------
// grid (NBl, Hh, Bsz); 256 threads: thread = (row r = tid>>1, half = tid&1)
// half splits the 128-key range for scores and the 64-d range for context.
#define SPAD 130   // score row stride; halves stored at col offsets 0 and 65
                   // -> bank(130*r + 65*h + t) = (tid + t) % 32, conflict-free

__global__ __launch_bounds__(256) void attn_kernel(
    const float* __restrict__ q, const float* __restrict__ k,
    const float* __restrict__ v, const int* __restrict__ layout,
    float* __restrict__ ctx)
{
    extern __shared__ float sm[];
    float* sKV  = sm;                     // 128*64
    float* sS   = sm + 128 * 64;          // 128*SPAD
    float* sRed = sS + 128 * SPAD;        // 256 (max halves) + 256 (sum halves)

    const int ib  = blockIdx.x;
    const int hh  = blockIdx.y;
    const int bb  = blockIdx.z;
    const int tid = threadIdx.x;
    const int r    = tid >> 1;
    const int half = tid & 1;

    const size_t qbase = ((size_t)(bb * Sseq + ib * BLKs)) * Dm + hh * DHd;

    // cooperative load of the q tile, then copy own row to registers
    {
        #pragma unroll
        for (int f = tid; f < 2048; f += 256) {
            const int row = f >> 4, c = (f & 15) << 2;
            *reinterpret_cast<float4*>(sKV + row * 64 + c) =
                *reinterpret_cast<const float4*>(q + qbase + (size_t)row * Dm + c);
        }
    }
    __syncthreads();
    float qreg[64];
    #pragma unroll
    for (int c = 0; c < 64; c += 4)
        *reinterpret_cast<float4*>(qreg + c) = *reinterpret_cast<float4*>(sKV + r * 64 + c);

    float m = -1e30f, l = 0.f;
    float cacc[32];
    #pragma unroll
    for (int d = 0; d < 32; d++) cacc[d] = 0.f;
    const float scale = 0.125f;   // DH^-0.5

    for (int j = 0; j <= ib; j++) {
        if (!layout[(hh * NBl + ib) * NBl + j]) continue;   // uniform branch

        __syncthreads();   // protect previous-iteration V reads (and q staging)
        // load K_j
        const size_t kbase = ((size_t)(bb * Sseq + j * BLKs)) * Dm + hh * DHd;
        #pragma unroll
        for (int f = tid; f < 2048; f += 256) {
            const int row = f >> 4, c = (f & 15) << 2;
            *reinterpret_cast<float4*>(sKV + row * 64 + c) =
                *reinterpret_cast<const float4*>(k + kbase + (size_t)row * Dm + c);
        }
        __syncthreads();

        // scores for this thread's 64 keys
        const int t0 = half * 64;
        float lmax = -1e30f;
        for (int tl = 0; tl < 64; tl++) {
            const int t = t0 + tl;
            float s;
            if (j < ib || t <= r) {
                float dot = 0.f;
                const float* kr = sKV + t * 64;
                #pragma unroll
                for (int d = 0; d < 64; d++) dot = fmaf(qreg[d], kr[d], dot);
                s = dot * scale;
            } else {
                s = -1e9f;
            }
            sS[r * SPAD + half * 65 + tl] = s;
            lmax = fmaxf(lmax, s);
        }
        sRed[r * 2 + half] = lmax;
        __syncthreads();   // scores done; K no longer needed

        // load V_j (overwrites K)
        #pragma unroll
        for (int f = tid; f < 2048; f += 256) {
            const int row = f >> 4, c = (f & 15) << 2;
            *reinterpret_cast<float4*>(sKV + row * 64 + c) =
                *reinterpret_cast<const float4*>(v + kbase + (size_t)row * Dm + c);
        }

        // online softmax update for own half
        const float mb   = fmaxf(sRed[r * 2], sRed[r * 2 + 1]);
        const float mnew = fmaxf(m, mb);
        const float corr = __expf(m - mnew);
        float lsum = 0.f;
        for (int tl = 0; tl < 64; tl++) {
            const int idx = r * SPAD + half * 65 + tl;
            const float p = __expf(sS[idx] - mnew);
            sS[idx] = p;
            lsum += p;
        }
        sRed[256 + r * 2 + half] = lsum;
        __syncthreads();   // V loaded + all p written

        l = l * corr + sRed[256 + r * 2] + sRed[256 + r * 2 + 1];
        #pragma unroll
        for (int d = 0; d < 32; d++) cacc[d] *= corr;
        for (int t = 0; t < 128; t++) {
            const float p = sS[r * SPAD + t + (t >> 6)];   // skip pad col 64
            const float* vr = sKV + t * 64 + half * 32;
            #pragma unroll
            for (int d = 0; d < 32; d++) cacc[d] = fmaf(p, vr[d], cacc[d]);
        }
        m = mnew;
    }

    const float inv = 1.f / l;
    float* dst = ctx + qbase + (size_t)r * Dm + half * 32;
    #pragma unroll
    for (int d = 0; d < 32; d += 4) {
        float4 o;
        o.x = cacc[d + 0] * inv; o.y = cacc[d + 1] * inv;
        o.z = cacc[d + 2] * inv; o.w = cacc[d + 3] * inv;
        *reinterpret_cast<float4*>(dst + d) = o;
    }
}

#define ATTN_SMEM (128 * 64 * 4 + 128 * SPAD * 4 + 512 * 4)

// ---------------------------------------------------------------------------
extern "C" void kernel_launch(void* const* d_in, const int* in_sizes, int n_in,
                              void* d_out, int out_size)
{
    (void)in_sizes; (void)n_in; (void)out_size;
    const float* x     = (const float*)d_in[0];
    const float* ln1_g = (const float*)d_in[1];
    const float* ln1_b = (const float*)d_in[2];
    const float* Wq    = (const float*)d_in[3];
    const float* bq    = (const float*)d_in[4];
    const float* Wk    = (const float*)d_in[5];
    const float* bk    = (const float*)d_in[6];
    const float* Wv    = (const float*)d_in[7];
    const float* bv    = (const float*)d_in[8];
    const float* Wo    = (const float*)d_in[9];
    const float* bo    = (const float*)d_in[10];
    const float* ln2_g = (const float*)d_in[11];
    const float* ln2_b = (const float*)d_in[12];
    const float* W1    = (const float*)d_in[13];
    const float* b1    = (const float*)d_in[14];
    const float* W2    = (const float*)d_in[15];
    const float* b2    = (const float*)d_in[16];
    const int*   lay   = (const int*)d_in[17];
    float* out = (float*)d_out;

    float *h, *q, *k, *v, *ctx, *x1, *h2, *ff;
    cudaGetSymbolAddress((void**)&h,   g_h);
    cudaGetSymbolAddress((void**)&q,   g_q);
    cudaGetSymbolAddress((void**)&k,   g_k);
    cudaGetSymbolAddress((void**)&v,   g_v);
    cudaGetSymbolAddress((void**)&ctx, g_ctx);
    cudaGetSymbolAddress((void**)&x1,  g_x1);
    cudaGetSymbolAddress((void**)&h2,  g_h2);
    cudaGetSymbolAddress((void**)&ff,  g_ff);

    cudaFuncSetAttribute(attn_kernel,
                         cudaFuncAttributeMaxDynamicSharedMemorySize, ATTN_SMEM);

    // 1) ln1
    ln_kernel<<<Mrows, 256>>>(x, ln1_g, ln1_b, h);

    // 2) QKV projections
    dim3 g1(Dm / 128, Mrows / 128);
    sgemm_kernel<0><<<g1, 256>>>(h, Wq, bq, nullptr, q, Mrows, Dm, Dm);
    sgemm_kernel<0><<<g1, 256>>>(h, Wk, bk, nullptr, k, Mrows, Dm, Dm);
    sgemm_kernel<0><<<g1, 256>>>(h, Wv, bv, nullptr, v, Mrows, Dm, Dm);

    // 3) block-sparse attention
    attn_kernel<<<dim3(NBl, Hh, Bsz), 256, ATTN_SMEM>>>(q, k, v, lay, ctx);

    // 4) output projection + residual
    sgemm_kernel<2><<<g1, 256>>>(ctx, Wo, bo, x, x1, Mrows, Dm, Dm);

    // 5) ln2
    ln_kernel<<<Mrows, 256>>>(x1, ln2_g, ln2_b, h2);

    // 6) MLP
    dim3 g2(Dff / 128, Mrows / 128);
    sgemm_kernel<1><<<g2, 256>>>(h2, W1, b1, nullptr, ff, Mrows, Dff, Dm);
    sgemm_kernel<2><<<g1, 256>>>(ff, W2, b2, x1, out, Mrows, Dm, Dff);
}

// round 3
// speedup vs baseline: 1.9662x; 1.9662x over previous
#include <cuda_runtime.h>
#include <math.h>
#include <stdint.h>

#define Bsz   2
#define Sseq  2048
#define Dm    1024
#define Hh    16
#define DHd   64
#define BLKs  128
#define NBl   16
#define Mrows (Bsz * Sseq)   // 4096
#define Dff   (4 * Dm)       // 4096

// ---------------- scratch ---------------------------------------------------
__device__ float g_h  [Mrows * Dm];
__device__ float g_q  [Mrows * Dm];
__device__ float g_k  [Mrows * Dm];
__device__ float g_v  [Mrows * Dm];
__device__ float g_ctx[Mrows * Dm];
__device__ float g_x1 [Mrows * Dm];
__device__ float g_h2 [Mrows * Dm];
__device__ float g_ff [Mrows * Dff];

// ---------------- helpers ---------------------------------------------------
__device__ __forceinline__ uint32_t smem_u32(const void* p) {
    uint32_t a;
    asm("{ .reg .u64 t; cvta.to.shared.u64 t, %1; cvt.u32.u64 %0, t; }"
        : "=r"(a) : "l"(p));
    return a;
}
__device__ __forceinline__ uint32_t cvt_tf32(float x) {
    uint32_t r;
    asm("cvt.rna.tf32.f32 %0, %1;" : "=r"(r) : "f"(x));
    return r;
}
__device__ __forceinline__ void cpa16(uint32_t dst, const void* src) {
    asm volatile("cp.async.cg.shared.global [%0], [%1], 16;" :: "r"(dst), "l"(src));
}
__device__ __forceinline__ float gelu_exact(float x) {
    return 0.5f * x * (1.0f + erff(x * 0.70710678118654752f));
}

// ---------------- mma.sync tf32 GEMM ----------------------------------------
// C[M,N] = A[M,K] @ W[K,N] (+bias / gelu / residual).  W row-major [K][N].
#define APADW 36
#define BPADW 136
#define ASTG_BYTES (128 * APADW * 4)          // 18432
#define BSTG_BYTES (32 * BPADW * 4)           // 17408
#define STG_BYTES  (ASTG_BYTES + BSTG_BYTES)  // 35840
#define MMA_SMEM   (2 * STG_BYTES)            // 71680

template<int EPI>
__global__ __launch_bounds__(256, 2) void mma_gemm(
    const float* __restrict__ A, const float* __restrict__ W,
    const float* __restrict__ bias, const float* __restrict__ res,
    float* __restrict__ C, int M, int N, int K)
{
    extern __shared__ char smem[];
    const uint32_t sbase = smem_u32(smem);
    const int tid = threadIdx.x;
    const int bm  = blockIdx.y * 128;
    const int bn  = blockIdx.x * 128;
    const int NK  = K >> 5;

    // cp.async geometry: A -> [row][k] pad 36 fl ; B -> [k][n] pad 136 fl
    const int arow = tid >> 1;              // 0..127
    const int ah   = tid & 1;               // half-row (16 floats each)
    const int brow = tid >> 3;              // 0..31 (k)
    const int bseg = tid & 7;               // 16-float segment in n

    const float* Ag0 = A + (size_t)(bm + arow) * K + ah * 16;
    const float* Bg0 = W + (size_t)brow * N + bn + bseg * 16;

    #define ISSUE_CHUNK(kt, st)                                                 \
    {   const uint32_t ab = sbase + (st) * STG_BYTES;                           \
        const float* ag = Ag0 + (size_t)(kt) * 32;                              \
        _Pragma("unroll")                                                       \
        for (int j = 0; j < 4; j++)                                             \
            cpa16(ab + arow * 144 + (ah * 4 + j) * 16, ag + j * 4);             \
        const uint32_t bb = ab + ASTG_BYTES;                                    \
        const float* bg = Bg0 + (size_t)(kt) * 32 * N;                          \
        _Pragma("unroll")                                                       \
        for (int j = 0; j < 4; j++)                                             \
            cpa16(bb + brow * 544 + (bseg * 4 + j) * 16, bg + j * 4);           \
        asm volatile("cp.async.commit_group;" ::: "memory");                    \
    }

    const int w    = tid >> 5, lane = tid & 31;
    const int wm   = (w >> 2) * 64;        // warp row base
    const int wn   = (w & 3) * 32;         // warp col base
    const int lr   = lane >> 2;            // 0..7
    const int lk   = lane & 3;             // 0..3

    float acc[4][4][4];
    #pragma unroll
    for (int i = 0; i < 4; i++)
        #pragma unroll
        for (int j = 0; j < 4; j++)
            #pragma unroll
            for (int c = 0; c < 4; c++) acc[i][j][c] = 0.f;

    ISSUE_CHUNK(0, 0);

    for (int kt = 0; kt < NK; kt++) {
        const int st = kt & 1;
        if (kt + 1 < NK) {
            ISSUE_CHUNK(kt + 1, st ^ 1);
            asm volatile("cp.async.wait_group 1;" ::: "memory");
        } else {
            asm volatile("cp.async.wait_group 0;" ::: "memory");
        }
        __syncthreads();

        const float* as = reinterpret_cast<const float*>(smem + st * STG_BYTES);
        const float* bs = as + 128 * APADW;

        #pragma unroll
        for (int s = 0; s < 4; s++) {
            const int k0 = s * 8 + lk;
            uint32_t af[4][4], bf[4][2];
            #pragma unroll
            for (int i = 0; i < 4; i++) {
                const int r = wm + i * 16 + lr;
                af[i][0] = cvt_tf32(as[r * APADW + k0]);
                af[i][1] = cvt_tf32(as[(r + 8) * APADW + k0]);
                af[i][2] = cvt_tf32(as[r * APADW + k0 + 4]);
                af[i][3] = cvt_tf32(as[(r + 8) * APADW + k0 + 4]);
            }
            #pragma unroll
            for (int j = 0; j < 4; j++) {
                const int n = wn + j * 8 + lr;
                bf[j][0] = cvt_tf32(bs[k0 * BPADW + n]);
                bf[j][1] = cvt_tf32(bs[(k0 + 4) * BPADW + n]);
            }
            #pragma unroll
            for (int i = 0; i < 4; i++)
                #pragma unroll
                for (int j = 0; j < 4; j++)
                    asm volatile(
                        "mma.sync.aligned.m16n8k8.row.col.f32.tf32.tf32.f32 "
                        "{%0,%1,%2,%3}, {%4,%5,%6,%7}, {%8,%9}, {%0,%1,%2,%3};"
                        : "+f"(acc[i][j][0]), "+f"(acc[i][j][1]),
                          "+f"(acc[i][j][2]), "+f"(acc[i][j][3])
                        : "r"(af[i][0]), "r"(af[i][1]), "r"(af[i][2]), "r"(af[i][3]),
                          "r"(bf[j][0]), "r"(bf[j][1]));
        }
        __syncthreads();
    }
    #undef ISSUE_CHUNK

    // epilogue: c0 (row, col), c1 (row, col+1), c2 (row+8, col), c3 (row+8, col+1)
    #pragma unroll
    for (int i = 0; i < 4; i++) {
        #pragma unroll
        for (int j = 0; j < 4; j++) {
            const int row0 = bm + wm + i * 16 + lr;
            const int col  = bn + wn + j * 8 + lk * 2;
            #pragma unroll
            for (int hrow = 0; hrow < 2; hrow++) {
                const int row = row0 + hrow * 8;
                float2 o;
                o.x = acc[i][j][hrow * 2 + 0] + bias[col + 0];
                o.y = acc[i][j][hrow * 2 + 1] + bias[col + 1];
                if (EPI == 1) { o.x = gelu_exact(o.x); o.y = gelu_exact(o.y); }
                if (EPI == 2) {
                    const float2 r2 = *reinterpret_cast<const float2*>(
                        res + (size_t)row * N + col);
                    o.x += r2.x; o.y += r2.y;
                }
                *reinterpret_cast<float2*>(C + (size_t)row * N + col) = o;
            }
        }
    }
}

// ---------------- LayerNorm -------------------------------------------------
__global__ __launch_bounds__(256) void ln_kernel(
    const float* __restrict__ x, const float* __restrict__ g,
    const float* __restrict__ b, float* __restrict__ out)
{
    const int row = blockIdx.x;
    const int t   = threadIdx.x;
    const float4 v = reinterpret_cast<const float4*>(x + (size_t)row * Dm)[t];

    float s  = v.x + v.y + v.z + v.w;
    float s2 = v.x * v.x + v.y * v.y + v.z * v.z + v.w * v.w;

    __shared__ float red[16];
    #pragma unroll
    for (int o = 16; o; o >>= 1) {
        s  += __shfl_xor_sync(0xffffffffu, s,  o);
        s2 += __shfl_xor_sync(0xffffffffu, s2, o);
    }
    const int w = t >> 5, l = t & 31;
    if (l == 0) { red[w] = s; red[w + 8] = s2; }
    __syncthreads();
    if (w == 0) {
        float a  = (l < 8) ? red[l]     : 0.f;
        float a2 = (l < 8) ? red[l + 8] : 0.f;
        #pragma unroll
        for (int o = 4; o; o >>= 1) {
            a  += __shfl_xor_sync(0xffffffffu, a,  o);
            a2 += __shfl_xor_sync(0xffffffffu, a2, o);
        }
        if (l == 0) { red[0] = a; red[1] = a2; }
    }
    __syncthreads();

    const float mean = red[0] * (1.f / Dm);
    const float var  = red[1] * (1.f / Dm) - mean * mean;
    const float rs   = rsqrtf(var + 1e-5f);

    const float4 gg = reinterpret_cast<const float4*>(g)[t];
    const float4 bb = reinterpret_cast<const float4*>(b)[t];
    float4 o4;
    o4.x = (v.x - mean) * rs * gg.x + bb.x;
    o4.y = (v.y - mean) * rs * gg.y + bb.y;
    o4.z = (v.z - mean) * rs * gg.z + bb.z;
    o4.w = (v.w - mean) * rs * gg.w + bb.w;
    reinterpret_cast<float4*>(out + (size_t)row * Dm)[t] = o4;
}

// ---------------- block-sparse flash attention ------------------------------
#define SPAD 130

__global__ __launch_bounds__(256) void attn_kernel(
    const float* __restrict__ q, const float* __restrict__ k,
    const float* __restrict__ v, const int* __restrict__ layout,
    float* __restrict__ ctx)
{
    extern __shared__ float sm[];
    float* sKV  = sm;
    float* sS   = sm + 128 * 64;
    float* sRed = sS + 128 * SPAD;

    const int ib  = blockIdx.x;
    const int hh  = blockIdx.y;
    const int bb  = blockIdx.z;
    const int tid = threadIdx.x;
    const int r    = tid >> 1;
    const int half = tid & 1;

    const size_t qbase = ((size_t)(bb * Sseq + ib * BLKs)) * Dm + hh * DHd;

    #pragma unroll
    for (int f = tid; f < 2048; f += 256) {
        const int row = f >> 4, c = (f & 15) << 2;
        *reinterpret_cast<float4*>(sKV + row * 64 + c) =
            *reinterpret_cast<const float4*>(q + qbase + (size_t)row * Dm + c);
    }
    __syncthreads();
    float qreg[64];
    #pragma unroll
    for (int c = 0; c < 64; c += 4)
        *reinterpret_cast<float4*>(qreg + c) = *reinterpret_cast<float4*>(sKV + r * 64 + c);

    float m = -1e30f, l = 0.f;
    float cacc[32];
    #pragma unroll
    for (int d = 0; d < 32; d++) cacc[d] = 0.f;
    const float scale = 0.125f;

    for (int j = 0; j <= ib; j++) {
        if (!layout[(hh * NBl + ib) * NBl + j]) continue;

        __syncthreads();
        const size_t kbase = ((size_t)(bb * Sseq + j * BLKs)) * Dm + hh * DHd;
        #pragma unroll
        for (int f = tid; f < 2048; f += 256) {
            const int row = f >> 4, c = (f & 15) << 2;
            *reinterpret_cast<float4*>(sKV + row * 64 + c) =
                *reinterpret_cast<const float4*>(k + kbase + (size_t)row * Dm + c);
        }
        __syncthreads();

        const int t0 = half * 64;
        float lmax = -1e30f;
        for (int tl = 0; tl < 64; tl++) {
            const int t = t0 + tl;
            float s;
            if (j < ib || t <= r) {
                float dot = 0.f;
                const float* kr = sKV + t * 64;
                #pragma unroll
                for (int d = 0; d < 64; d++) dot = fmaf(qreg[d], kr[d], dot);
                s = dot * scale;
            } else {
                s = -1e9f;
            }
            sS[r * SPAD + half * 65 + tl] = s;
            lmax = fmaxf(lmax, s);
        }
        sRed[r * 2 + half] = lmax;
        __syncthreads();

        #pragma unroll
        for (int f = tid; f < 2048; f += 256) {
            const int row = f >> 4, c = (f & 15) << 2;
            *reinterpret_cast<float4*>(sKV + row * 64 + c) =
                *reinterpret_cast<const float4*>(v + kbase + (size_t)row * Dm + c);
        }

        const float mb   = fmaxf(sRed[r * 2], sRed[r * 2 + 1]);
        const float mnew = fmaxf(m, mb);
        const float corr = __expf(m - mnew);
        float lsum = 0.f;
        for (int tl = 0; tl < 64; tl++) {
            const int idx = r * SPAD + half * 65 + tl;
            const float p = __expf(sS[idx] - mnew);
            sS[idx] = p;
            lsum += p;
        }
        sRed[256 + r * 2 + half] = lsum;
        __syncthreads();

        l = l * corr + sRed[256 + r * 2] + sRed[256 + r * 2 + 1];
        #pragma unroll
        for (int d = 0; d < 32; d++) cacc[d] *= corr;
        for (int t = 0; t < 128; t++) {
            const float p = sS[r * SPAD + t + (t >> 6)];
            const float* vr = sKV + t * 64 + half * 32;
            #pragma unroll
            for (int d = 0; d < 32; d++) cacc[d] = fmaf(p, vr[d], cacc[d]);
        }
        m = mnew;
    }

    const float inv = 1.f / l;
    float* dst = ctx + qbase + (size_t)r * Dm + half * 32;
    #pragma unroll
    for (int d = 0; d < 32; d += 4) {
        float4 o;
        o.x = cacc[d + 0] * inv; o.y = cacc[d + 1] * inv;
        o.z = cacc[d + 2] * inv; o.w = cacc[d + 3] * inv;
        *reinterpret_cast<float4*>(dst + d) = o;
    }
}

#define ATTN_SMEM (128 * 64 * 4 + 128 * SPAD * 4 + 512 * 4)

// ---------------------------------------------------------------------------
extern "C" void kernel_launch(void* const* d_in, const int* in_sizes, int n_in,
                              void* d_out, int out_size)
{
    (void)in_sizes; (void)n_in; (void)out_size;
    const float* x     = (const float*)d_in[0];
    const float* ln1_g = (const float*)d_in[1];
    const float* ln1_b = (const float*)d_in[2];
    const float* Wq    = (const float*)d_in[3];
    const float* bq    = (const float*)d_in[4];
    const float* Wk    = (const float*)d_in[5];
    const float* bk    = (const float*)d_in[6];
    const float* Wv    = (const float*)d_in[7];
    const float* bv    = (const float*)d_in[8];
    const float* Wo    = (const float*)d_in[9];
    const float* bo    = (const float*)d_in[10];
    const float* ln2_g = (const float*)d_in[11];
    const float* ln2_b = (const float*)d_in[12];
    const float* W1    = (const float*)d_in[13];
    const float* b1    = (const float*)d_in[14];
    const float* W2    = (const float*)d_in[15];
    const float* b2    = (const float*)d_in[16];
    const int*   lay   = (const int*)d_in[17];
    float* out = (float*)d_out;

    float *h, *q, *k, *v, *ctx, *x1, *h2, *ff;
    cudaGetSymbolAddress((void**)&h,   g_h);
    cudaGetSymbolAddress((void**)&q,   g_q);
    cudaGetSymbolAddress((void**)&k,   g_k);
    cudaGetSymbolAddress((void**)&v,   g_v);
    cudaGetSymbolAddress((void**)&ctx, g_ctx);
    cudaGetSymbolAddress((void**)&x1,  g_x1);
    cudaGetSymbolAddress((void**)&h2,  g_h2);
    cudaGetSymbolAddress((void**)&ff,  g_ff);

    cudaFuncSetAttribute(attn_kernel,
                         cudaFuncAttributeMaxDynamicSharedMemorySize, ATTN_SMEM);
    cudaFuncSetAttribute(mma_gemm<0>,
                         cudaFuncAttributeMaxDynamicSharedMemorySize, MMA_SMEM);
    cudaFuncSetAttribute(mma_gemm<1>,
                         cudaFuncAttributeMaxDynamicSharedMemorySize, MMA_SMEM);
    cudaFuncSetAttribute(mma_gemm<2>,
                         cudaFuncAttributeMaxDynamicSharedMemorySize, MMA_SMEM);

    // 1) ln1
    ln_kernel<<<Mrows, 256>>>(x, ln1_g, ln1_b, h);

    // 2) QKV projections
    dim3 g1(Dm / 128, Mrows / 128);
    mma_gemm<0><<<g1, 256, MMA_SMEM>>>(h, Wq, bq, nullptr, q, Mrows, Dm, Dm);
    mma_gemm<0><<<g1, 256, MMA_SMEM>>>(h, Wk, bk, nullptr, k, Mrows, Dm, Dm);
    mma_gemm<0><<<g1, 256, MMA_SMEM>>>(h, Wv, bv, nullptr, v, Mrows, Dm, Dm);

    // 3) block-sparse attention
    attn_kernel<<<dim3(NBl, Hh, Bsz), 256, ATTN_SMEM>>>(q, k, v, lay, ctx);

    // 4) output projection + residual
    mma_gemm<2><<<g1, 256, MMA_SMEM>>>(ctx, Wo, bo, x, x1, Mrows, Dm, Dm);

    // 5) ln2
    ln_kernel<<<Mrows, 256>>>(x1, ln2_g, ln2_b, h2);

    // 6) MLP
    dim3 g2(Dff / 128, Mrows / 128);
    mma_gemm<1><<<g2, 256, MMA_SMEM>>>(h2, W1, b1, nullptr, ff, Mrows, Dff, Dm);
    mma_gemm<2><<<g1, 256, MMA_SMEM>>>(ff, W2, b2, x1, out, Mrows, Dm, Dff);
}